// round 16
// baseline (speedup 1.0000x reference)
#include <cuda_runtime.h>

#define NN 32
#define CC 256
#define SS 30
#define HWD 256        // 16*16 pixels per frame
#define PP 16          // parts
#define PIT 260        // row pitch: 16B-aligned, 2-way worst-case LDS
#define WCH 4          // channels per warp
#define STC 2          // channels per subtile
#define NST 2          // subtiles per warp
#define SLICES 8       // channel slices per frame (block = 8 warps x 4 ch = 32)

#define CP_ASYNC16(dst, src) \
    asm volatile("cp.async.cg.shared.global [%0], [%1], 16;" :: "r"(dst), "l"(src) : "memory")
#define CP_COMMIT() asm volatile("cp.async.commit_group;" ::: "memory")
#define CP_WAIT(n)  asm volatile("cp.async.wait_group %0;" :: "n"(n) : "memory")

__global__ __launch_bounds__(256, 6)
void part_pool_kernel(const float* __restrict__ x,
                      const void* __restrict__ labels_raw,
                      float* __restrict__ out)
{
    extern __shared__ float tiles[];      // 8 warps * WCH * PIT floats = 33,280 B
    __shared__ unsigned int pk4w[(HWD + PP * 4) / 4];  // byte pixel lists, 4-aligned starts
    __shared__ int off4[PP], fill[PP];

    unsigned char* pk4 = (unsigned char*)pk4w;

    const int bid = blockIdx.x;           // 0..7679
    const int f   = bid >> 3;             // frame
    const int q   = bid & 7;              // channel slice (32 channels)
    const int n = f / SS;
    const int s = f % SS;
    const int t = threadIdx.x;
    const int w = t >> 5;
    const int l = t & 31;

    // warp-private tile region and channel range
    float* wbase = tiles + w * (WCH * PIT);
    const unsigned swb = (unsigned)__cvta_generic_to_shared(wbase);
    const int cbase = q * (8 * WCH) + w * WCH;    // first channel of this warp

    // load roles: lanes 0-15 -> subtile channel 0, lanes 16-31 -> channel 1
    const int lch = l >> 4;
    const int lg  = l & 15;
    #define LOAD_SUB(st) do {                                                  \
        const float* _row = x + ((size_t)(n * CC + cbase + (st) * STC + lch)   \
                                 * SS + s) * HWD;                              \
        unsigned _dst = swb + (unsigned)(((st) * STC + lch) * (PIT * 4));      \
        _Pragma("unroll")                                                      \
        for (int _k = 0; _k < 4; _k++) {                                       \
            int _g = lg + 16 * _k;                                             \
            CP_ASYNC16(_dst + _g * 16, _row + _g * 4);                         \
        }                                                                      \
        CP_COMMIT();                                                           \
    } while (0)

    // ---- issue BOTH subtile loads before the prologue (no label dependence):
    // overlaps all bucketing latency with this warp's 4 KB of DRAM traffic.
    LOAD_SUB(0);
    LOAD_SUB(1);

    // ---- fused label-dtype detection (frame-0 region, in-bounds both layouts):
    // int64 little-endian labels 0..15 -> odd 32-bit words all zero.
    if (t < PP) fill[t] = 0;
    const int oddw = ((const int*)labels_raw)[2 * t + 1];
    const int lab64 = !__syncthreads_or(oddw != 0);   // also orders fill init

    // ---- per-frame label bucketing (single atomic phase) ----
    int myl;
    if (lab64) myl = (int)((const long long*)labels_raw)[(size_t)f * HWD + t];
    else       myl = ((const int*)labels_raw)[(size_t)f * HWD + t];
    myl &= (PP - 1);
    const int pos = atomicAdd(&fill[myl], 1);
    __syncthreads();                      // fill[p] == cnt[p] final

    if (t == 0) {
        int acc = 0;
        #pragma unroll
        for (int pp = 0; pp < PP; pp++) { off4[pp] = acc; acc += (fill[pp] + 3) & ~3; }
    }
    __syncthreads();                      // off4[] ready
    pk4[off4[myl] + pos] = (unsigned char)t;   // byte pixel list write
    __syncthreads();                      // pk4 visible; LAST block barrier

    // ---- warp-autonomous main phase: zero block barriers below ----
    // compute roles: lane = (part l>>1, channel l&1); lane pairs share a list
    const int p  = l >> 1;
    const int ch = l & 1;
    const int cN = fill[p];
    const float rc = (cN > 0) ? (1.0f / (float)cN) : 0.0f;
    const unsigned int* mylist = pk4w + (off4[p] >> 2);
    const int kW = cN >> 2;               // full 4-pixel words
    const int kR = cN & 3;                // tail pixels in final word

    #pragma unroll
    for (int st = 0; st < NST; st++) {
        if (st == 0) CP_WAIT(1);          // subtile 0 landed (sub 1 in flight)
        else         CP_WAIT(0);
        __syncwarp();                     // publish lanes' copies warp-wide

        const float* tb = wbase + (st * STC + ch) * PIT;

        float sum = 0.0f;
        float mx  = -3.0e38f;
        #pragma unroll 2
        for (int k = 0; k < kW; k++) {
            unsigned u = mylist[k];       // broadcast LDS (lane pair): 4 pixel ids
            float a = tb[u & 255u];
            float b = tb[(u >> 8) & 255u];
            float c = tb[(u >> 16) & 255u];
            float d = tb[u >> 24];
            sum += (a + b) + (c + d);
            mx = fmaxf(fmaxf(fmaxf(a, b), fmaxf(c, d)), mx);
        }
        if (kR) {                         // tail: only written bytes extracted
            unsigned u = mylist[kW];
            #pragma unroll
            for (int j = 0; j < 3; j++) {
                if (j < kR) {
                    float v = tb[(u >> (8 * j)) & 255u];
                    sum += v;
                    mx = fmaxf(mx, v);
                }
            }
        }

        float r = 0.0f;
        if (cN > 0)
            r = sum * rc + fmaxf(mx, -100.0f);  // mean + amax(incl -100 init)

        // store: lanes with ch=0 cover parts 0..15 of one channel -> 64B
        // contiguous per half of the warp's lanes; 4 sectors total per warp.
        int c = cbase + st * STC + ch;
        out[((size_t)(n * CC + c) * SS + s) * PP + p] = r;
    }
    #undef LOAD_SUB
}

extern "C" void kernel_launch(void* const* d_in, const int* in_sizes, int n_in,
                              void* d_out, int out_size)
{
    const float* x      = (const float*)d_in[0];
    const void*  labels = d_in[1];
    float*       out    = (float*)d_out;

    cudaFuncSetAttribute(part_pool_kernel,
                         cudaFuncAttributeMaxDynamicSharedMemorySize,
                         8 * WCH * PIT * 4);

    part_pool_kernel<<<NN * SS * SLICES, 256, 8 * WCH * PIT * 4>>>(x, labels, out);
}

// round 17
// speedup vs baseline: 1.5572x; 1.5572x over previous
#include <cuda_runtime.h>

#define NN 32
#define CC 256
#define SS 30
#define HWD 256        // 16*16 pixels per frame
#define PP 16          // parts
#define CT 16          // channels per tile
#define PIT 260        // pitch: 16B-aligned rows, 2-way worst-case LDS
#define TILES 2        // tiles per block (block covers 32 channels)
#define SLICES 8       // channel slices per frame

#define CP_ASYNC16(dst, src) \
    asm volatile("cp.async.cg.shared.global.L2::256B [%0], [%1], 16;" :: "r"(dst), "l"(src) : "memory")
#define CP_COMMIT() asm volatile("cp.async.commit_group;" ::: "memory")
#define CP_WAIT(n)  asm volatile("cp.async.wait_group %0;" :: "n"(n) : "memory")

__global__ __launch_bounds__(256, 6)
void part_pool_kernel(const float* __restrict__ x,
                      const void* __restrict__ labels_raw,
                      float* __restrict__ out)
{
    extern __shared__ float tiles[];      // 2 * CT*PIT floats = 33,280 B
    __shared__ float pooled[CT * 17];
    __shared__ unsigned int pk4w[(HWD + PP * 4) / 4];  // byte pixel lists, 4-aligned starts
    __shared__ int off4[PP], fill[PP];

    unsigned char* pk4 = (unsigned char*)pk4w;

    const int bid = blockIdx.x;           // 0..7679
    const int f   = bid >> 3;             // frame
    const int q   = bid & 7;              // channel slice (32 channels)
    const int n = f / SS;
    const int s = f % SS;
    const int t = threadIdx.x;
    const int w = t >> 5;
    const int l = t & 31;

    // base of this block's channel range for frame (n,s)
    const float* xf = x + ((size_t)(n * CC + q * (TILES * CT)) * SS + s) * HWD;
    const unsigned stile = (unsigned)__cvta_generic_to_shared(tiles);

    // 16B cp.async: thread t loads channel t>>4, 4 groups of 4 pixels (coalesced)
    const int lcl = t >> 4;
    const int lg  = t & 15;
    #define LOAD_TILE(tt, buf) do {                                            \
        const float* _row = xf + (size_t)((tt) * CT + lcl) * (SS * HWD);       \
        unsigned _dst = stile + (unsigned)(((buf) * CT + lcl) * (PIT * 4));    \
        _Pragma("unroll")                                                      \
        for (int _k = 0; _k < 4; _k++) {                                       \
            int _g = lg + 16 * _k;                                             \
            CP_ASYNC16(_dst + _g * 16, _row + _g * 4);                         \
        }                                                                      \
        CP_COMMIT();                                                           \
    } while (0)

    // ---- issue both tile loads BEFORE the prologue (no label dependence):
    // overlaps all bucketing latency with the first 32 KB of DRAM traffic.
    LOAD_TILE(0, 0);
    LOAD_TILE(1, 1);

    // ---- fused label-dtype detection (frame-0 region, in-bounds both layouts):
    // int64 little-endian labels 0..15 -> odd 32-bit words all zero.
    if (t < PP) fill[t] = 0;
    const int oddw = ((const int*)labels_raw)[2 * t + 1];
    const int lab64 = !__syncthreads_or(oddw != 0);   // also orders fill init

    // ---- per-frame label bucketing (single atomic phase) ----
    int myl;
    if (lab64) myl = (int)((const long long*)labels_raw)[(size_t)f * HWD + t];
    else       myl = ((const int*)labels_raw)[(size_t)f * HWD + t];
    myl &= (PP - 1);
    const int pos = atomicAdd(&fill[myl], 1);
    __syncthreads();                      // fill[p] == cnt[p] final

    // per-lane fixed roles: half-warp owns one part, lane&15 = channel in tile
    const int p  = (w << 1) | (l >> 4);   // part 0..15
    const int cl = l & 15;                // channel-in-tile
    const int cN = fill[p];
    const float rc = (cN > 0) ? (1.0f / (float)cN) : 0.0f;

    if (t == 0) {
        int acc = 0;
        #pragma unroll
        for (int pp = 0; pp < PP; pp++) { off4[pp] = acc; acc += (fill[pp] + 3) & ~3; }
    }
    __syncthreads();                      // off4[] ready
    pk4[off4[myl] + pos] = (unsigned char)t;   // byte pixel list write
    // pk4 visibility to other warps: covered by the first tile-ready sync.

    const unsigned int* mylist = pk4w + (off4[p] >> 2);
    const int kW = cN >> 2;               // full 4-pixel words
    const int kR = cN & 3;                // tail pixels in final word

    for (int tt = 0; tt < TILES; tt++) {
        const int buf = tt & 1;
        if (tt + 1 < TILES) CP_WAIT(1);   // tile tt landed (one newer in flight)
        else                CP_WAIT(0);
        __syncthreads();                  // tile tt visible to all

        const float* tb = tiles + (buf * CT + cl) * PIT;

        float sum = 0.0f;
        float mx  = -3.0e38f;
        #pragma unroll 2
        for (int k = 0; k < kW; k++) {
            unsigned u = mylist[k];       // 1 broadcast LDS -> 4 pixel ids
            float a = tb[u & 255u];
            float b = tb[(u >> 8) & 255u];
            float c = tb[(u >> 16) & 255u];
            float d = tb[u >> 24];
            sum += (a + b) + (c + d);
            mx = fmaxf(fmaxf(fmaxf(a, b), fmaxf(c, d)), mx);
        }
        if (kR) {                         // tail: only written bytes extracted
            unsigned u = mylist[kW];
            #pragma unroll
            for (int j = 0; j < 3; j++) {
                if (j < kR) {
                    float v = tb[(u >> (8 * j)) & 255u];
                    sum += v;
                    mx = fmaxf(mx, v);
                }
            }
        }

        float r = 0.0f;
        if (cN > 0)
            r = sum * rc + fmaxf(mx, -100.0f);  // mean + amax(incl -100 init)
        pooled[cl * 17 + p] = r;

        __syncthreads();                  // pooled ready AND buffer tt reads done

        // coalesced store: thread t -> (channel t>>4, part t&15)
        {
            int cc = t >> 4;
            int pp = t & 15;
            int c  = q * (TILES * CT) + tt * CT + cc;
            out[((size_t)(n * CC + c) * SS + s) * PP + pp] = pooled[cc * 17 + pp];
        }

        // refill this buffer with tile tt+2 (no-op for TILES=2)
        if (tt + 2 < TILES) LOAD_TILE(tt + 2, buf);
    }
    #undef LOAD_TILE
}

extern "C" void kernel_launch(void* const* d_in, const int* in_sizes, int n_in,
                              void* d_out, int out_size)
{
    const float* x      = (const float*)d_in[0];
    const void*  labels = d_in[1];
    float*       out    = (float*)d_out;

    cudaFuncSetAttribute(part_pool_kernel,
                         cudaFuncAttributeMaxDynamicSharedMemorySize,
                         2 * CT * PIT * 4);

    part_pool_kernel<<<NN * SS * SLICES, 256, 2 * CT * PIT * 4>>>(x, labels, out);
}